// round 2
// baseline (speedup 1.0000x reference)
#include <cuda_runtime.h>

// Problem constants (fixed shapes from the reference)
#define NE      513          // NUM_EDGES + 1
#define LHOPS   5
#define HEADS   8
#define FEAT    64
#define NPAIRS  (8*128*128)  // B*N*N = 131072
#define HALF_ELEMS (LHOPS*NE*4)       // one head-half slice: 10260 floats = 41040 B
#define PAIRS_PER_BLK 886             // ceil(131072 / 148)

// Projection table in head-split layout: g_proj[hp][(l*NE+e)*4 + c], h = hp*4+c
__device__ __align__(16) float g_proj[2 * HALF_ELEMS];

// Kernel A: proj[l][e][h] = sum_f edge_emb[e][f] * attn_w[l][f][h],
// written into the split layout above.
__global__ void proj_kernel(const float* __restrict__ emb,
                            const float* __restrict__ w) {
    int gid = blockIdx.x * blockDim.x + threadIdx.x;
    if (gid >= LHOPS * NE * HEADS) return;
    int h   = gid & (HEADS - 1);
    int row = gid >> 3;              // l*NE + e
    int l   = row / NE;
    int e   = row - l * NE;
    const float* er = emb + e * FEAT;
    const float* wr = w + l * FEAT * HEADS + h;
    float acc = 0.f;
    #pragma unroll
    for (int f = 0; f < FEAT; ++f)
        acc = fmaf(er[f], wr[f * HEADS], acc);
    int hp = h >> 2;
    int c  = h & 3;
    g_proj[hp * HALF_ELEMS + row * 4 + c] = acc;
}

// Kernel B: 2 CTAs per SM (one per head-half), each stages a 41 KB table slice
// into static smem and computes 4 heads for a contiguous chunk of pairs:
//   out[pair][hp*4+c] = (0.5/dist[pair]) * sum_{l,d} proj[hp][l][pd[pair][l][d]][c]
// Handles both int64 and int32 index/dist dtypes (runtime-detected).
__global__ void __launch_bounds__(1024, 2)
enc_kernel(const void* __restrict__ distp,
           const void* __restrict__ pdp,
           float* __restrict__ out) {
    __shared__ float s_proj[HALF_ELEMS];  // 41040 B static smem

    const int tid = threadIdx.x;
    const int hp  = blockIdx.x & 1;       // which head-half this CTA computes
    const int blk = blockIdx.x >> 1;      // pair-chunk index (0..147)

    // cooperative vectorized slice load (10260 floats = 2565 float4)
    {
        const float4* gsrc = (const float4*)(g_proj + hp * HALF_ELEMS);
        float4* sdst = (float4*)s_proj;
        for (int i = tid; i < HALF_ELEMS / 4; i += 1024)
            sdst[i] = gsrc[i];
    }
    __syncthreads();

    const int pair = blk * PAIRS_PER_BLK + tid;
    if (tid >= PAIRS_PER_BLK || pair >= NPAIRS) return;

    // dtype detection: dist values are in [1,5]. If stored as int64 (LE),
    // int32 word #1 is the high half of dist[0] == 0; if int32 it's dist[1]!=0.
    const bool is64 = (((const int*)distp)[1] == 0);

    int idx[2 * LHOPS];
    float scale;
    if (is64) {
        // 10 int64 = 80 bytes contiguous, 16B-aligned (80 = 5*16)
        const int4* p = (const int4*)((const long long*)pdp + (size_t)pair * 10);
        #pragma unroll
        for (int j = 0; j < 5; ++j) {
            int4 v = p[j];               // two int64: low words are .x and .z
            idx[2 * j]     = v.x;
            idx[2 * j + 1] = v.z;
        }
        scale = 0.5f / (float)((const long long*)distp)[pair];
    } else {
        // 10 int32 = 40 bytes contiguous, 8B-aligned
        const int2* p = (const int2*)((const int*)pdp + (size_t)pair * 10);
        #pragma unroll
        for (int j = 0; j < 5; ++j) {
            int2 v = p[j];
            idx[2 * j]     = v.x;
            idx[2 * j + 1] = v.y;
        }
        scale = 0.5f / (float)((const int*)distp)[pair];
    }

    float4 a = make_float4(0.f, 0.f, 0.f, 0.f);
    #pragma unroll
    for (int j = 0; j < 2 * LHOPS; ++j) {
        int l = j >> 1;                  // path_data layout [...,L,D]: j = l*2+d
        const float4 r =
            *(const float4*)(s_proj + (size_t)(l * NE + idx[j]) * 4);
        a.x += r.x; a.y += r.y; a.z += r.z; a.w += r.w;
    }

    float4* o = (float4*)(out + (size_t)pair * HEADS + hp * 4);
    *o = make_float4(a.x * scale, a.y * scale, a.z * scale, a.w * scale);
}

extern "C" void kernel_launch(void* const* d_in, const int* in_sizes, int n_in,
                              void* d_out, int out_size) {
    const void*  dist = d_in[0];
    const void*  pd   = d_in[1];
    const float* emb  = (const float*)d_in[2];
    const float* w    = (const float*)d_in[3];

    proj_kernel<<<(LHOPS * NE * HEADS + 255) / 256, 256>>>(emb, w);
    enc_kernel<<<296, 1024>>>(dist, pd, (float*)d_out);
}